// round 4
// baseline (speedup 1.0000x reference)
#include <cuda_runtime.h>
#include <cstdint>
#include <cstdio>

// ---------------------------------------------------------------------------
// Problem constants (from reference)
// ---------------------------------------------------------------------------
#define NROWS 8192
#define FDIM  512
#define HDIM  1024
#define STEPS 50
#define NELEM (NROWS * FDIM)          // 4194304

// ---------------------------------------------------------------------------
// Scratch (device globals: allocation-free rule)
// ---------------------------------------------------------------------------
__device__ float g_x[NROWS * FDIM];        // current diffusion state
__device__ float g_qf[NROWS * HDIM];       // relu(x@Wq+bq)
__device__ float g_h[NROWS * HDIM];        // reused hidden (h0 / h1 / hi)
__device__ float g_cat[NROWS * HDIM];      // [d0 | d1] concatenated
__device__ float g_interf[NROWS * FDIM];   // interference output

__device__ float g_sp0, g_sp1, g_p0, g_u;
__device__ float g_cA[STEPS];       // (1-alpha)/sqrt(1-alpha)
__device__ float g_rsqa[STEPS];     // 1/sqrt(alpha)
__device__ float g_qi[STEPS];       // quantum interference scalar
__device__ float g_ncoef[STEPS];    // sigma + 0.1*|qi| (0 when t==0)
__device__ unsigned g_key[STEPS][2];
__device__ unsigned g_key_init[2];

// ---------------------------------------------------------------------------
// Threefry-2x32 (JAX-compatible, 20 rounds)
// ---------------------------------------------------------------------------
__device__ __forceinline__ void tf2x32(unsigned k0, unsigned k1,
                                       unsigned x0, unsigned x1,
                                       unsigned& o0, unsigned& o1) {
    unsigned ks2 = k0 ^ k1 ^ 0x1BD11BDAu;
    x0 += k0; x1 += k1;
#define TF_RND(r) { x0 += x1; x1 = __funnelshift_l(x1, x1, (r)); x1 ^= x0; }
    TF_RND(13) TF_RND(15) TF_RND(26) TF_RND(6)
    x0 += k1;  x1 += ks2 + 1u;
    TF_RND(17) TF_RND(29) TF_RND(16) TF_RND(24)
    x0 += ks2; x1 += k0 + 2u;
    TF_RND(13) TF_RND(15) TF_RND(26) TF_RND(6)
    x0 += k0;  x1 += k1 + 3u;
    TF_RND(17) TF_RND(29) TF_RND(16) TF_RND(24)
    x0 += k1;  x1 += ks2 + 4u;
    TF_RND(13) TF_RND(15) TF_RND(26) TF_RND(6)
    x0 += ks2; x1 += k0 + 5u;
#undef TF_RND
    o0 = x0; o1 = x1;
}

// Partitionable-mode random bits for element i (i < 2^32):
// block = (hi=0, lo=i), bits = out0 ^ out1
__device__ __forceinline__ unsigned tf_bits_partitionable(unsigned k0, unsigned k1,
                                                          unsigned i) {
    unsigned o0, o1;
    tf2x32(k0, k1, 0u, i, o0, o1);
    return o0 ^ o1;
}

// bits -> standard normal, mirroring jax.random.normal:
// u in [0,1) from top 23 bits; v = max(lo, u*2 + lo) with lo = nextafter(-1,0)
// (hi-lo rounds to exactly 2.0f in fp32); z = sqrt(2)*erfinv(v)
__device__ __forceinline__ float bits_to_normal(unsigned b) {
    float u = __uint_as_float((b >> 9) | 0x3f800000u) - 1.0f;
    const float LO = -0.99999994f;
    float v = fmaxf(fmaf(u, 2.0f, LO), LO);
    return 1.41421356f * erfinvf(v);
}

// ---------------------------------------------------------------------------
// Prep kernel: per-step scalars, per-step Threefry keys, measurement u
// ---------------------------------------------------------------------------
__global__ void prep_kernel(const float* __restrict__ alpha_amp,
                            const float* __restrict__ beta_amp,
                            const float* __restrict__ phase_cos) {
    int s = threadIdx.x;
    float A = *alpha_amp, B = *beta_amp, pc = *phase_cos;
    float a2 = A * A, b2 = B * B;
    float p0 = a2 / (a2 + b2);
    float p1 = b2 / (a2 + b2);

    if (s == 0) { g_p0 = p0; g_sp0 = sqrtf(p0); g_sp1 = sqrtf(p1); }

    if (s < STEPS) {
        int t = (STEPS - 1) - s;
        const float delta = (0.02f - 1e-4f) / 99.0f;   // linspace(1e-4,0.02,100) step
        float sched_t = 1e-4f + (float)t * delta;
        float alpha = fmaxf(1.0f - sched_t, 1e-8f);
        float alpha_prev;
        if (t > 0) {
            float sched_tm1 = 1e-4f + (float)(t - 1) * delta;
            alpha_prev = 1.0f - sched_tm1;
        } else {
            alpha_prev = 1.0f;
        }
        float one_m_a = 1.0f - alpha;
        float sqrt_1ma = sqrtf(fmaxf(one_m_a, 1e-8f));
        g_cA[s]   = one_m_a / sqrt_1ma;
        g_rsqa[s] = 1.0f / sqrtf(alpha);

        // coherence = decay^s via iterative fp32 multiply (matches scan carry)
        float decay = expf(-0.1f);
        float coh = 1.0f;
        for (int i = 0; i < s; i++) coh *= decay;
        float qi = 2.0f * sqrtf(p0 * p1) * pc * coh;
        g_qi[s] = qi;

        float sig2 = (1.0f - alpha_prev) / (1.0f - alpha) * (1.0f - alpha / alpha_prev);
        float sigma = sqrtf(fmaxf(sig2, 0.0f));
        g_ncoef[s] = (t > 0) ? (sigma + 0.1f * fabsf(qi)) : 0.0f;

        unsigned o0, o1;                 // fold_in(key(1), t) = TF((0,1),(0,t))
        tf2x32(0u, 1u, 0u, (unsigned)t, o0, o1);
        g_key[s][0] = o0; g_key[s][1] = o1;
    }
    if (s == STEPS) {                    // x0 key: fold_in(key(1), 10000)
        unsigned o0, o1;
        tf2x32(0u, 1u, 0u, 10000u, o0, o1);
        g_key_init[0] = o0; g_key_init[1] = o1;
    }
    if (s == STEPS + 1) {                // measurement u: fold_in(key(1), 99999)
        unsigned k0, k1;
        tf2x32(0u, 1u, 0u, 99999u, k0, k1);
        unsigned b = tf_bits_partitionable(k0, k1, 0u);   // scalar: block (0,0)
        g_u = __uint_as_float((b >> 9) | 0x3f800000u) - 1.0f;
    }
}

// ---------------------------------------------------------------------------
// x0 = normal(fold_in(key, 10000), (8192, 512)) — partitionable bit stream
// ---------------------------------------------------------------------------
__global__ __launch_bounds__(256) void init_kernel() {
    int j = blockIdx.x * 256 + threadIdx.x;
    unsigned k0 = g_key_init[0], k1 = g_key_init[1];
    g_x[j] = bits_to_normal(tf_bits_partitionable(k0, k1, (unsigned)j));
}

// ---------------------------------------------------------------------------
// Generic SGEMM: C[:, col_off + n] = act(A[M,K] @ W[K,Nc] + bias), row-major.
// 128x128 block tile, BK=16, 256 threads, 8x8 per thread.
// ACT: 0=none 1=relu 2=tanh 3=gelu(exact)
// ---------------------------------------------------------------------------
#define BM 128
#define BN 128
#define BK 16

template <int ACT>
__global__ __launch_bounds__(256, 2)
void sgemm_kernel(const float* __restrict__ A, const float* __restrict__ W,
                  const float* __restrict__ bias, float* __restrict__ C,
                  int K, int Nc, int ldc, int col_off) {
    __shared__ float As[BK][BM];
    __shared__ float Bs[BK][BN];

    const int m0 = blockIdx.y * BM;
    const int n0 = blockIdx.x * BN;
    const int tid = threadIdx.x;
    const int tm = tid >> 4;   // 0..15
    const int tn = tid & 15;   // 0..15

    float acc[8][8];
#pragma unroll
    for (int i = 0; i < 8; i++)
#pragma unroll
        for (int j = 0; j < 8; j++) acc[i][j] = 0.0f;

    for (int k0 = 0; k0 < K; k0 += BK) {
        // A tile: 128 rows x 16 cols, stored transposed As[k][m]
#pragma unroll
        for (int i = 0; i < 2; i++) {
            int idx = tid + i * 256;          // 0..511
            int r = idx >> 2, c4 = idx & 3;
            float4 v = *(const float4*)(A + (size_t)(m0 + r) * K + k0 + c4 * 4);
            As[c4 * 4 + 0][r] = v.x;
            As[c4 * 4 + 1][r] = v.y;
            As[c4 * 4 + 2][r] = v.z;
            As[c4 * 4 + 3][r] = v.w;
        }
        // B tile: 16 rows x 128 cols
#pragma unroll
        for (int i = 0; i < 2; i++) {
            int idx = tid + i * 256;
            int r = idx >> 5, c4 = idx & 31;
            *(float4*)(&Bs[r][c4 * 4]) =
                *(const float4*)(W + (size_t)(k0 + r) * Nc + n0 + c4 * 4);
        }
        __syncthreads();

#pragma unroll
        for (int k = 0; k < BK; k++) {
            float a[8], b[8];
#pragma unroll
            for (int i = 0; i < 8; i++) a[i] = As[k][tm * 8 + i];
#pragma unroll
            for (int j = 0; j < 8; j++) b[j] = Bs[k][tn * 8 + j];
#pragma unroll
            for (int i = 0; i < 8; i++)
#pragma unroll
                for (int j = 0; j < 8; j++)
                    acc[i][j] = fmaf(a[i], b[j], acc[i][j]);
        }
        __syncthreads();
    }

    float bv[8];
#pragma unroll
    for (int j = 0; j < 8; j++) bv[j] = bias[n0 + tn * 8 + j];

#pragma unroll
    for (int i = 0; i < 8; i++) {
        float* crow = C + (size_t)(m0 + tm * 8 + i) * ldc + col_off + n0 + tn * 8;
#pragma unroll
        for (int j = 0; j < 8; j++) {
            float v = acc[i][j] + bv[j];
            if (ACT == 1) v = fmaxf(v, 0.0f);
            else if (ACT == 2) v = tanhf(v);
            else if (ACT == 3) v = 0.5f * v * (1.0f + erff(v * 0.70710678f));
            crow[j] = v;
        }
    }
}

// ---------------------------------------------------------------------------
// Fused diffusion update + Threefry noise (partitionable stream)
// x = (x - cA*(sp0*d0 + sp1*d1 + qi*interf)) * rsqa  [+ ncoef * noise_t]
// ---------------------------------------------------------------------------
__global__ __launch_bounds__(256) void update_kernel(int s) {
    int j = blockIdx.x * 256 + threadIdx.x;
    float sp0 = g_sp0, sp1 = g_sp1;
    float qi = g_qi[s], cA = g_cA[s], rsqa = g_rsqa[s], nc = g_ncoef[s];

    int row = j >> 9, col = j & 511;
    float d0 = g_cat[(row << 10) + col];
    float d1 = g_cat[(row << 10) + 512 + col];
    float den = sp0 * d0 + sp1 * d1 + qi * g_interf[j];
    float xn = (g_x[j] - cA * den) * rsqa;
    if (nc != 0.0f) {
        unsigned b = tf_bits_partitionable(g_key[s][0], g_key[s][1], (unsigned)j);
        xn += nc * bits_to_normal(b);
    }
    g_x[j] = xn;
}

// ---------------------------------------------------------------------------
// Measurement collapse
// ---------------------------------------------------------------------------
__global__ __launch_bounds__(256) void final_kernel(const float* __restrict__ real,
                                                    float* __restrict__ out) {
    int i = blockIdx.x * 256 + threadIdx.x;
    float x = g_x[i];
    out[i] = (g_u < g_p0) ? (0.7f * x + 0.3f * real[i]) : x;
}

// ---------------------------------------------------------------------------
// Launch
// ---------------------------------------------------------------------------
extern "C" void kernel_launch(void* const* d_in, const int* in_sizes, int n_in,
                              void* d_out, int out_size) {
    const float *real, *Wq, *bq, *W01, *b01, *W02, *b02, *W11, *b11;
    const float *W12, *b12, *Wi1, *bi1, *Wi2, *bi2, *a_amp, *b_amp, *pc;

    if (in_sizes[0] == NELEM) {
        // metadata in dict-insertion order; steps scalar may or may not be present
        int o = (n_in >= 2 && in_sizes[1] == 1) ? 2 : 1;
        real = (const float*)d_in[0];
        Wq   = (const float*)d_in[o + 0];  bq  = (const float*)d_in[o + 1];
        W01  = (const float*)d_in[o + 2];  b01 = (const float*)d_in[o + 3];
        W02  = (const float*)d_in[o + 4];  b02 = (const float*)d_in[o + 5];
        W11  = (const float*)d_in[o + 6];  b11 = (const float*)d_in[o + 7];
        W12  = (const float*)d_in[o + 8];  b12 = (const float*)d_in[o + 9];
        Wi1  = (const float*)d_in[o + 10]; bi1 = (const float*)d_in[o + 11];
        Wi2  = (const float*)d_in[o + 12]; bi2 = (const float*)d_in[o + 13];
        a_amp = (const float*)d_in[o + 14];
        b_amp = (const float*)d_in[o + 15];
        pc    = (const float*)d_in[o + 16];
    } else {
        // alphabetical order: W01,W02,W11,W12,Wi1,Wi2,Wq,alpha_amp,b01,b02,
        // b11,b12,beta_amp,bi1,bi2,bq,phase_cos,real_antigen[,steps]
        W01 = (const float*)d_in[0];  W02 = (const float*)d_in[1];
        W11 = (const float*)d_in[2];  W12 = (const float*)d_in[3];
        Wi1 = (const float*)d_in[4];  Wi2 = (const float*)d_in[5];
        Wq  = (const float*)d_in[6];  a_amp = (const float*)d_in[7];
        b01 = (const float*)d_in[8];  b02 = (const float*)d_in[9];
        b11 = (const float*)d_in[10]; b12 = (const float*)d_in[11];
        b_amp = (const float*)d_in[12];
        bi1 = (const float*)d_in[13]; bi2 = (const float*)d_in[14];
        bq  = (const float*)d_in[15]; pc  = (const float*)d_in[16];
        real = (const float*)d_in[17];
    }
    float* out = (float*)d_out;

    void *px, *pqf, *ph, *pcat, *pint;
    cudaGetSymbolAddress(&px,  g_x);
    cudaGetSymbolAddress(&pqf, g_qf);
    cudaGetSymbolAddress(&ph,  g_h);
    cudaGetSymbolAddress(&pcat, g_cat);
    cudaGetSymbolAddress(&pint, g_interf);
    float* x   = (float*)px;
    float* qf  = (float*)pqf;
    float* h   = (float*)ph;
    float* cat = (float*)pcat;
    float* itf = (float*)pint;

    prep_kernel<<<1, 64>>>(a_amp, b_amp, pc);
    init_kernel<<<NELEM / 256, 256>>>();

    dim3 gH(HDIM / BN, NROWS / BM);   // outputs of width 1024
    dim3 gF(FDIM / BN, NROWS / BM);   // outputs of width 512

    for (int s = 0; s < STEPS; s++) {
        // qf = relu(x @ Wq + bq)                      [8192,1024]
        sgemm_kernel<1><<<gH, 256>>>(x, Wq, bq, qf, FDIM, HDIM, HDIM, 0);
        // h0 = relu(qf @ W01 + b01)                   [8192,1024]
        sgemm_kernel<1><<<gH, 256>>>(qf, W01, b01, h, HDIM, HDIM, HDIM, 0);
        // d0 = h0 @ W02 + b02  -> cat[:, 0:512]
        sgemm_kernel<0><<<gF, 256>>>(h, W02, b02, cat, HDIM, FDIM, HDIM, 0);
        // h1 = tanh(qf @ W11 + b11)
        sgemm_kernel<2><<<gH, 256>>>(qf, W11, b11, h, HDIM, HDIM, HDIM, 0);
        // d1 = h1 @ W12 + b12  -> cat[:, 512:1024]
        sgemm_kernel<0><<<gF, 256>>>(h, W12, b12, cat, HDIM, FDIM, HDIM, FDIM);
        // hi = gelu(cat @ Wi1 + bi1)
        sgemm_kernel<3><<<gH, 256>>>(cat, Wi1, bi1, h, 2 * FDIM, HDIM, HDIM, 0);
        // interf = hi @ Wi2 + bi2
        sgemm_kernel<0><<<gF, 256>>>(h, Wi2, bi2, itf, HDIM, FDIM, FDIM, 0);
        // diffusion update + noise
        update_kernel<<<NELEM / 256, 256>>>(s);
    }

    final_kernel<<<NELEM / 256, 256>>>(real, out);
}

// round 8
// speedup vs baseline: 2.6782x; 2.6782x over previous
#include <cuda_runtime.h>
#include <cuda_bf16.h>
#include <cstdint>
#include <cstdio>

// ---------------------------------------------------------------------------
// Problem constants
// ---------------------------------------------------------------------------
#define NROWS 8192
#define FDIM  512
#define HDIM  1024
#define STEPS 50
#define NELEM (NROWS * FDIM)          // 4194304

// ---------------------------------------------------------------------------
// Scratch (device globals: allocation-free rule)
// ---------------------------------------------------------------------------
__device__ float         g_x[NELEM];                    // fp32 diffusion state
__device__ __nv_bfloat16 g_xh[NELEM],  g_xl[NELEM];     // split of x
__device__ __nv_bfloat16 g_qfh[NROWS * HDIM], g_qfl[NROWS * HDIM];
__device__ __nv_bfloat16 g_hh[NROWS * HDIM],  g_hl[NROWS * HDIM];
__device__ __nv_bfloat16 g_cath[NROWS * HDIM], g_catl[NROWS * HDIM];
__device__ float         g_interf[NELEM];

// transposed + split weights (B operands, K-major [N,K])
__device__ __nv_bfloat16 g_WqTh[HDIM * FDIM],  g_WqTl[HDIM * FDIM];
__device__ __nv_bfloat16 g_W01Th[HDIM * HDIM], g_W01Tl[HDIM * HDIM];
__device__ __nv_bfloat16 g_W02Th[FDIM * HDIM], g_W02Tl[FDIM * HDIM];
__device__ __nv_bfloat16 g_W11Th[HDIM * HDIM], g_W11Tl[HDIM * HDIM];
__device__ __nv_bfloat16 g_W12Th[FDIM * HDIM], g_W12Tl[FDIM * HDIM];
__device__ __nv_bfloat16 g_Wi1Th[HDIM * HDIM], g_Wi1Tl[HDIM * HDIM];
__device__ __nv_bfloat16 g_Wi2Th[FDIM * HDIM], g_Wi2Tl[FDIM * HDIM];

__device__ float g_sp0, g_sp1, g_p0, g_u;
__device__ float g_cA[STEPS], g_rsqa[STEPS], g_qi[STEPS], g_ncoef[STEPS];
__device__ unsigned g_key[STEPS][2];
__device__ unsigned g_key_init[2];

// ---------------------------------------------------------------------------
// PTX helpers (baseline ISA only — compute_103 target has no tcgen05)
// ---------------------------------------------------------------------------
__device__ __forceinline__ uint32_t smem_to_u32(const void* p) {
    uint32_t a;
    asm("{ .reg .u64 t; cvta.to.shared.u64 t, %1; cvt.u32.u64 %0, t; }"
        : "=r"(a) : "l"(p));
    return a;
}
__device__ __forceinline__ void cp16(uint32_t dst, const void* src) {
    asm volatile("cp.async.cg.shared.global [%0], [%1], 16;"
                 :: "r"(dst), "l"(src) : "memory");
}
#define CP_COMMIT() asm volatile("cp.async.commit_group;" ::: "memory")
#define LDSM4(R, addr) \
    asm volatile("ldmatrix.sync.aligned.m8n8.x4.shared.b16 {%0,%1,%2,%3}, [%4];" \
                 : "=r"((R)[0]), "=r"((R)[1]), "=r"((R)[2]), "=r"((R)[3]) : "r"(addr))
__device__ __forceinline__ void mma_bf16(float* d, const uint32_t* a, const uint32_t* b) {
    asm volatile("mma.sync.aligned.m16n8k16.row.col.f32.bf16.bf16.f32 "
                 "{%0,%1,%2,%3}, {%4,%5,%6,%7}, {%8,%9}, {%0,%1,%2,%3};"
                 : "+f"(d[0]), "+f"(d[1]), "+f"(d[2]), "+f"(d[3])
                 : "r"(a[0]), "r"(a[1]), "r"(a[2]), "r"(a[3]), "r"(b[0]), "r"(b[1]));
}

// ---------------------------------------------------------------------------
// Threefry-2x32 (JAX partitionable mode)
// ---------------------------------------------------------------------------
__device__ __forceinline__ void tf2x32(unsigned k0, unsigned k1,
                                       unsigned x0, unsigned x1,
                                       unsigned& o0, unsigned& o1) {
    unsigned ks2 = k0 ^ k1 ^ 0x1BD11BDAu;
    x0 += k0; x1 += k1;
#define TF_RND(r) { x0 += x1; x1 = __funnelshift_l(x1, x1, (r)); x1 ^= x0; }
    TF_RND(13) TF_RND(15) TF_RND(26) TF_RND(6)
    x0 += k1;  x1 += ks2 + 1u;
    TF_RND(17) TF_RND(29) TF_RND(16) TF_RND(24)
    x0 += ks2; x1 += k0 + 2u;
    TF_RND(13) TF_RND(15) TF_RND(26) TF_RND(6)
    x0 += k0;  x1 += k1 + 3u;
    TF_RND(17) TF_RND(29) TF_RND(16) TF_RND(24)
    x0 += k1;  x1 += ks2 + 4u;
    TF_RND(13) TF_RND(15) TF_RND(26) TF_RND(6)
    x0 += ks2; x1 += k0 + 5u;
#undef TF_RND
    o0 = x0; o1 = x1;
}
__device__ __forceinline__ unsigned tf_bits(unsigned k0, unsigned k1, unsigned i) {
    unsigned o0, o1;
    tf2x32(k0, k1, 0u, i, o0, o1);
    return o0 ^ o1;
}
__device__ __forceinline__ float bits_to_normal(unsigned b) {
    float u = __uint_as_float((b >> 9) | 0x3f800000u) - 1.0f;
    const float LO = -0.99999994f;
    float v = fmaxf(fmaf(u, 2.0f, LO), LO);
    return 1.41421356f * erfinvf(v);
}
__device__ __forceinline__ void split_bf16(float v, __nv_bfloat16& h, __nv_bfloat16& l) {
    h = __float2bfloat16(v);
    l = __float2bfloat16(v - __bfloat162float(h));
}

// ---------------------------------------------------------------------------
// Prep: per-step scalars, keys, measurement u
// ---------------------------------------------------------------------------
__global__ void prep_kernel(const float* __restrict__ alpha_amp,
                            const float* __restrict__ beta_amp,
                            const float* __restrict__ phase_cos) {
    int s = threadIdx.x;
    float A = *alpha_amp, B = *beta_amp, pc = *phase_cos;
    float a2 = A * A, b2 = B * B;
    float p0 = a2 / (a2 + b2), p1 = b2 / (a2 + b2);
    if (s == 0) { g_p0 = p0; g_sp0 = sqrtf(p0); g_sp1 = sqrtf(p1); }
    if (s < STEPS) {
        int t = (STEPS - 1) - s;
        const float delta = (0.02f - 1e-4f) / 99.0f;
        float sched_t = 1e-4f + (float)t * delta;
        float alpha = fmaxf(1.0f - sched_t, 1e-8f);
        float alpha_prev = (t > 0) ? (1.0f - (1e-4f + (float)(t - 1) * delta)) : 1.0f;
        float one_m_a = 1.0f - alpha;
        g_cA[s]   = one_m_a / sqrtf(fmaxf(one_m_a, 1e-8f));
        g_rsqa[s] = 1.0f / sqrtf(alpha);
        float decay = expf(-0.1f);
        float coh = 1.0f;
        for (int i = 0; i < s; i++) coh *= decay;
        float qi = 2.0f * sqrtf(p0 * p1) * pc * coh;
        g_qi[s] = qi;
        float sig2 = (1.0f - alpha_prev) / (1.0f - alpha) * (1.0f - alpha / alpha_prev);
        g_ncoef[s] = (t > 0) ? (sqrtf(fmaxf(sig2, 0.0f)) + 0.1f * fabsf(qi)) : 0.0f;
        unsigned o0, o1;
        tf2x32(0u, 1u, 0u, (unsigned)t, o0, o1);
        g_key[s][0] = o0; g_key[s][1] = o1;
    }
    if (s == STEPS) {
        unsigned o0, o1;
        tf2x32(0u, 1u, 0u, 10000u, o0, o1);
        g_key_init[0] = o0; g_key_init[1] = o1;
    }
    if (s == STEPS + 1) {
        unsigned k0, k1;
        tf2x32(0u, 1u, 0u, 99999u, k0, k1);
        unsigned b = tf_bits(k0, k1, 0u);
        g_u = __uint_as_float((b >> 9) | 0x3f800000u) - 1.0f;
    }
}

// ---------------------------------------------------------------------------
// Weight transpose + bf16 split:  W[K,N] -> WT_hi/lo[N,K]
// ---------------------------------------------------------------------------
__global__ __launch_bounds__(256) void wprep_kernel(const float* __restrict__ W,
                                                    __nv_bfloat16* __restrict__ Th,
                                                    __nv_bfloat16* __restrict__ Tl,
                                                    int K, int N) {
    int i = blockIdx.x * 256 + threadIdx.x;
    if (i >= K * N) return;
    int k = i / N, n = i - k * N;
    __nv_bfloat16 h, l;
    split_bf16(W[i], h, l);
    Th[(size_t)n * K + k] = h;
    Tl[(size_t)n * K + k] = l;
}

// ---------------------------------------------------------------------------
// x0 init: normal + split
// ---------------------------------------------------------------------------
__global__ __launch_bounds__(256) void init_kernel() {
    int j = blockIdx.x * 256 + threadIdx.x;
    float v = bits_to_normal(tf_bits(g_key_init[0], g_key_init[1], (unsigned)j));
    g_x[j] = v;
    split_bf16(v, g_xh[j], g_xl[j]);
}

// ---------------------------------------------------------------------------
// bf16 HMMA GEMM (mma.sync m16n8k16), 3-product compensation.
// C = act(A @ B^T + bias);  A split [M,Ka], B split [N,Ka], both K-major.
// CTA 128x128, BK=32, 8 warps (2x4), warp tile 64x32; cp.async double buffer.
// SMEM stage: Ah(0) Al(10240) Bh(20480) Bl(30720); row pad 40 bf16 (80B).
// ---------------------------------------------------------------------------
#define SM_STAGE 40960
#define SMEM_TOTAL (2 * SM_STAGE)

template <int ACT, int OUTF32>
__global__ __launch_bounds__(256)
void mm_kernel(const __nv_bfloat16* __restrict__ Ah, const __nv_bfloat16* __restrict__ Al,
               int Ka,
               const __nv_bfloat16* __restrict__ Bh, const __nv_bfloat16* __restrict__ Bl,
               const float* __restrict__ bias,
               float* __restrict__ Cf,
               __nv_bfloat16* __restrict__ Ch, __nv_bfloat16* __restrict__ Cl,
               int ldc, int col_off) {
    extern __shared__ char smem[];
    const uint32_t sb = smem_to_u32(smem);
    const int tid = threadIdx.x, lane = tid & 31, wid = tid >> 5;
    const int wr = wid >> 2, wc = wid & 3;            // warp grid 2x4
    const int m0 = blockIdx.y * 128, n0 = blockIdx.x * 128;
    const int NC = Ka / 32;

    float acc[4][4][4];
#pragma unroll
    for (int i = 0; i < 4; i++)
#pragma unroll
        for (int j = 0; j < 4; j++)
#pragma unroll
            for (int q = 0; q < 4; q++) acc[i][j][q] = 0.0f;

    // ---- async stage loader: 2 chunks/thread/matrix -------------------------
    auto issue = [&](int c) {
        int k0 = c * 32;
        uint32_t so = sb + (c & 1) * SM_STAGE;
#pragma unroll
        for (int i = 0; i < 2; i++) {
            int idx = tid + i * 256;              // 0..511
            int r = idx >> 2, cc = idx & 3;       // row 0..127, 16B chunk 0..3
            uint32_t d = so + r * 80 + cc * 16;
            size_t go = (size_t)r * Ka + k0 + cc * 8;
            cp16(d,           Ah + (size_t)m0 * Ka + go);
            cp16(d + 10240,   Al + (size_t)m0 * Ka + go);
            cp16(d + 20480,   Bh + (size_t)n0 * Ka + go);
            cp16(d + 30720,   Bl + (size_t)n0 * Ka + go);
        }
        CP_COMMIT();
    };

    issue(0);
    if (NC > 1) issue(1);

    for (int c = 0; c < NC; c++) {
        if (c + 1 < NC) asm volatile("cp.async.wait_group 1;" ::: "memory");
        else            asm volatile("cp.async.wait_group 0;" ::: "memory");
        __syncthreads();

        uint32_t so = sb + (c & 1) * SM_STAGE;
#pragma unroll
        for (int ks = 0; ks < 2; ks++) {
            // A fragments (hi & lo): row = wr*64 + mt*16 + (lane&15), col = ks*16+(lane>>4)*8
            uint32_t ah[4][4], al[4][4];
            {
                int arow = wr * 64 + (lane & 15);
                uint32_t acol = (uint32_t)(ks * 16 + ((lane >> 4) << 3)) * 2;
#pragma unroll
                for (int mt = 0; mt < 4; mt++) {
                    uint32_t ad = so + (uint32_t)(arow + mt * 16) * 80 + acol;
                    LDSM4(ah[mt], ad);
                    LDSM4(al[mt], ad + 10240);
                }
            }
            // B fragments: pair p covers n8 tiles 2p,2p+1
            uint32_t bh[2][4], bl[2][4];
            {
                int g = lane >> 3;
                int brow = wc * 32 + (lane & 7) + ((g >> 1) << 3);
                uint32_t bcol = (uint32_t)(ks * 16 + ((g & 1) << 3)) * 2;
#pragma unroll
                for (int p = 0; p < 2; p++) {
                    uint32_t bd = so + 20480 + (uint32_t)(brow + p * 16) * 80 + bcol;
                    LDSM4(bh[p], bd);
                    LDSM4(bl[p], bd + 10240);
                }
            }
#pragma unroll
            for (int mt = 0; mt < 4; mt++)
#pragma unroll
                for (int nt = 0; nt < 4; nt++) {
                    const uint32_t* bhp = &bh[nt >> 1][(nt & 1) * 2];
                    const uint32_t* blp = &bl[nt >> 1][(nt & 1) * 2];
                    mma_bf16(acc[mt][nt], ah[mt], bhp);   // Ah*Bh
                    mma_bf16(acc[mt][nt], ah[mt], blp);   // Ah*Bl
                    mma_bf16(acc[mt][nt], al[mt], bhp);   // Al*Bh
                }
        }
        __syncthreads();
        if (c + 2 < NC) issue(c + 2);
    }

    // ---- epilogue ----------------------------------------------------------
#pragma unroll
    for (int nt = 0; nt < 4; nt++) {
        int colg = n0 + wc * 32 + nt * 8 + (lane & 3) * 2;
        float b0 = bias[colg], b1 = bias[colg + 1];
#pragma unroll
        for (int mt = 0; mt < 4; mt++) {
            int r0 = m0 + wr * 64 + mt * 16 + (lane >> 2);
            float v[4];
            v[0] = acc[mt][nt][0] + b0;
            v[1] = acc[mt][nt][1] + b1;
            v[2] = acc[mt][nt][2] + b0;
            v[3] = acc[mt][nt][3] + b1;
#pragma unroll
            for (int q = 0; q < 4; q++) {
                if (ACT == 1) v[q] = fmaxf(v[q], 0.0f);
                else if (ACT == 2) v[q] = tanhf(v[q]);
                else if (ACT == 3) v[q] = 0.5f * v[q] * (1.0f + erff(v[q] * 0.70710678f));
            }
            if (OUTF32) {
                float2* p0 = (float2*)(Cf + (size_t)r0 * ldc + col_off + colg);
                float2* p1 = (float2*)(Cf + (size_t)(r0 + 8) * ldc + col_off + colg);
                *p0 = make_float2(v[0], v[1]);
                *p1 = make_float2(v[2], v[3]);
            } else {
                __nv_bfloat16 h0, l0, h1, l1;
                split_bf16(v[0], h0, l0);
                split_bf16(v[1], h1, l1);
                uint32_t hp = (uint32_t)__bfloat16_as_ushort(h0) |
                              ((uint32_t)__bfloat16_as_ushort(h1) << 16);
                uint32_t lp = (uint32_t)__bfloat16_as_ushort(l0) |
                              ((uint32_t)__bfloat16_as_ushort(l1) << 16);
                *(uint32_t*)(Ch + (size_t)r0 * ldc + col_off + colg) = hp;
                *(uint32_t*)(Cl + (size_t)r0 * ldc + col_off + colg) = lp;
                split_bf16(v[2], h0, l0);
                split_bf16(v[3], h1, l1);
                hp = (uint32_t)__bfloat16_as_ushort(h0) |
                     ((uint32_t)__bfloat16_as_ushort(h1) << 16);
                lp = (uint32_t)__bfloat16_as_ushort(l0) |
                     ((uint32_t)__bfloat16_as_ushort(l1) << 16);
                *(uint32_t*)(Ch + (size_t)(r0 + 8) * ldc + col_off + colg) = hp;
                *(uint32_t*)(Cl + (size_t)(r0 + 8) * ldc + col_off + colg) = lp;
            }
        }
    }
}

// ---------------------------------------------------------------------------
// Fused diffusion update + Threefry noise; writes x fp32 + bf16 split
// ---------------------------------------------------------------------------
__global__ __launch_bounds__(256) void update_kernel(int s) {
    int j = blockIdx.x * 256 + threadIdx.x;
    float sp0 = g_sp0, sp1 = g_sp1;
    float qi = g_qi[s], cA = g_cA[s], rsqa = g_rsqa[s], nc = g_ncoef[s];

    int row = j >> 9, col = j & 511;
    int base = (row << 10) + col;
    float d0 = __bfloat162float(g_cath[base])       + __bfloat162float(g_catl[base]);
    float d1 = __bfloat162float(g_cath[base + 512]) + __bfloat162float(g_catl[base + 512]);
    float den = sp0 * d0 + sp1 * d1 + qi * g_interf[j];
    float xn = (g_x[j] - cA * den) * rsqa;
    if (nc != 0.0f)
        xn += nc * bits_to_normal(tf_bits(g_key[s][0], g_key[s][1], (unsigned)j));
    g_x[j] = xn;
    split_bf16(xn, g_xh[j], g_xl[j]);
}

__global__ __launch_bounds__(256) void final_kernel(const float* __restrict__ real,
                                                    float* __restrict__ out) {
    int i = blockIdx.x * 256 + threadIdx.x;
    float x = g_x[i];
    out[i] = (g_u < g_p0) ? (0.7f * x + 0.3f * real[i]) : x;
}

// ---------------------------------------------------------------------------
// Launch
// ---------------------------------------------------------------------------
extern "C" void kernel_launch(void* const* d_in, const int* in_sizes, int n_in,
                              void* d_out, int out_size) {
    const float *real, *Wq, *bq, *W01, *b01, *W02, *b02, *W11, *b11;
    const float *W12, *b12, *Wi1, *bi1, *Wi2, *bi2, *a_amp, *b_amp, *pc;

    if (in_sizes[0] == NELEM) {
        int o = (n_in >= 2 && in_sizes[1] == 1) ? 2 : 1;
        real = (const float*)d_in[0];
        Wq   = (const float*)d_in[o + 0];  bq  = (const float*)d_in[o + 1];
        W01  = (const float*)d_in[o + 2];  b01 = (const float*)d_in[o + 3];
        W02  = (const float*)d_in[o + 4];  b02 = (const float*)d_in[o + 5];
        W11  = (const float*)d_in[o + 6];  b11 = (const float*)d_in[o + 7];
        W12  = (const float*)d_in[o + 8];  b12 = (const float*)d_in[o + 9];
        Wi1  = (const float*)d_in[o + 10]; bi1 = (const float*)d_in[o + 11];
        Wi2  = (const float*)d_in[o + 12]; bi2 = (const float*)d_in[o + 13];
        a_amp = (const float*)d_in[o + 14];
        b_amp = (const float*)d_in[o + 15];
        pc    = (const float*)d_in[o + 16];
    } else {
        W01 = (const float*)d_in[0];  W02 = (const float*)d_in[1];
        W11 = (const float*)d_in[2];  W12 = (const float*)d_in[3];
        Wi1 = (const float*)d_in[4];  Wi2 = (const float*)d_in[5];
        Wq  = (const float*)d_in[6];  a_amp = (const float*)d_in[7];
        b01 = (const float*)d_in[8];  b02 = (const float*)d_in[9];
        b11 = (const float*)d_in[10]; b12 = (const float*)d_in[11];
        b_amp = (const float*)d_in[12];
        bi1 = (const float*)d_in[13]; bi2 = (const float*)d_in[14];
        bq  = (const float*)d_in[15]; pc  = (const float*)d_in[16];
        real = (const float*)d_in[17];
    }
    float* out = (float*)d_out;

    void *p;
    #define SYM(var, sym) cudaGetSymbolAddress(&p, sym); auto* var = (__nv_bfloat16*)p;
    SYM(xh, g_xh)   SYM(xl, g_xl)
    SYM(qfh, g_qfh) SYM(qfl, g_qfl)
    SYM(hh, g_hh)   SYM(hl, g_hl)
    SYM(cath, g_cath) SYM(catl, g_catl)
    SYM(WqTh, g_WqTh)   SYM(WqTl, g_WqTl)
    SYM(W01Th, g_W01Th) SYM(W01Tl, g_W01Tl)
    SYM(W02Th, g_W02Th) SYM(W02Tl, g_W02Tl)
    SYM(W11Th, g_W11Th) SYM(W11Tl, g_W11Tl)
    SYM(W12Th, g_W12Th) SYM(W12Tl, g_W12Tl)
    SYM(Wi1Th, g_Wi1Th) SYM(Wi1Tl, g_Wi1Tl)
    SYM(Wi2Th, g_Wi2Th) SYM(Wi2Tl, g_Wi2Tl)
    #undef SYM
    cudaGetSymbolAddress(&p, g_interf); float* itf = (float*)p;

    cudaFuncSetAttribute(mm_kernel<1, 0>, cudaFuncAttributeMaxDynamicSharedMemorySize, SMEM_TOTAL);
    cudaFuncSetAttribute(mm_kernel<2, 0>, cudaFuncAttributeMaxDynamicSharedMemorySize, SMEM_TOTAL);
    cudaFuncSetAttribute(mm_kernel<3, 0>, cudaFuncAttributeMaxDynamicSharedMemorySize, SMEM_TOTAL);
    cudaFuncSetAttribute(mm_kernel<0, 0>, cudaFuncAttributeMaxDynamicSharedMemorySize, SMEM_TOTAL);
    cudaFuncSetAttribute(mm_kernel<0, 1>, cudaFuncAttributeMaxDynamicSharedMemorySize, SMEM_TOTAL);

    prep_kernel<<<1, 64>>>(a_amp, b_amp, pc);
    init_kernel<<<NELEM / 256, 256>>>();

    // one-time weight transpose+split
    wprep_kernel<<<(FDIM * HDIM + 255) / 256, 256>>>(Wq,  WqTh,  WqTl,  FDIM, HDIM);
    wprep_kernel<<<(HDIM * HDIM + 255) / 256, 256>>>(W01, W01Th, W01Tl, HDIM, HDIM);
    wprep_kernel<<<(HDIM * FDIM + 255) / 256, 256>>>(W02, W02Th, W02Tl, HDIM, FDIM);
    wprep_kernel<<<(HDIM * HDIM + 255) / 256, 256>>>(W11, W11Th, W11Tl, HDIM, HDIM);
    wprep_kernel<<<(HDIM * FDIM + 255) / 256, 256>>>(W12, W12Th, W12Tl, HDIM, FDIM);
    wprep_kernel<<<(HDIM * HDIM + 255) / 256, 256>>>(Wi1, Wi1Th, Wi1Tl, HDIM, HDIM);
    wprep_kernel<<<(HDIM * FDIM + 255) / 256, 256>>>(Wi2, Wi2Th, Wi2Tl, HDIM, FDIM);

    dim3 gH(HDIM / 128, NROWS / 128);   // (8, 64)
    dim3 gF(FDIM / 128, NROWS / 128);   // (4, 64)

    for (int s = 0; s < STEPS; s++) {
        // qf = relu(x @ Wq + bq)
        mm_kernel<1, 0><<<gH, 256, SMEM_TOTAL>>>(xh, xl, FDIM, WqTh, WqTl, bq,
                                                 nullptr, qfh, qfl, HDIM, 0);
        // h0 = relu(qf @ W01 + b01)
        mm_kernel<1, 0><<<gH, 256, SMEM_TOTAL>>>(qfh, qfl, HDIM, W01Th, W01Tl, b01,
                                                 nullptr, hh, hl, HDIM, 0);
        // d0 = h0 @ W02 + b02 -> cat[:, 0:512]
        mm_kernel<0, 0><<<gF, 256, SMEM_TOTAL>>>(hh, hl, HDIM, W02Th, W02Tl, b02,
                                                 nullptr, cath, catl, HDIM, 0);
        // h1 = tanh(qf @ W11 + b11)
        mm_kernel<2, 0><<<gH, 256, SMEM_TOTAL>>>(qfh, qfl, HDIM, W11Th, W11Tl, b11,
                                                 nullptr, hh, hl, HDIM, 0);
        // d1 = h1 @ W12 + b12 -> cat[:, 512:1024]
        mm_kernel<0, 0><<<gF, 256, SMEM_TOTAL>>>(hh, hl, HDIM, W12Th, W12Tl, b12,
                                                 nullptr, cath, catl, HDIM, FDIM);
        // hg = gelu(cat @ Wi1 + bi1)
        mm_kernel<3, 0><<<gH, 256, SMEM_TOTAL>>>(cath, catl, HDIM, Wi1Th, Wi1Tl, bi1,
                                                 nullptr, hh, hl, HDIM, 0);
        // interf = hg @ Wi2 + bi2  (fp32 out)
        mm_kernel<0, 1><<<gF, 256, SMEM_TOTAL>>>(hh, hl, HDIM, Wi2Th, Wi2Tl, bi2,
                                                 itf, nullptr, nullptr, FDIM, 0);
        // diffusion update + noise
        update_kernel<<<NELEM / 256, 256>>>(s);
    }

    final_kernel<<<NELEM / 256, 256>>>(real, out);
}

// round 9
// speedup vs baseline: 6.1179x; 2.2843x over previous
#include <cuda_runtime.h>
#include <cuda_fp16.h>
#include <cstdint>
#include <cstdio>

// ---------------------------------------------------------------------------
// Problem constants
// ---------------------------------------------------------------------------
#define NROWS 8192
#define FDIM  512
#define HDIM  1024
#define STEPS 50
#define NELEM (NROWS * FDIM)          // 4194304

// ---------------------------------------------------------------------------
// Scratch (device globals: allocation-free rule)
// ---------------------------------------------------------------------------
__device__ float  g_x[NELEM];                 // fp32 diffusion state
__device__ __half g_xh[NELEM];                // fp16 of x (GEMM input)
__device__ __half g_qfh[NROWS * HDIM];
__device__ __half g_hh[NROWS * HDIM];
__device__ __half g_cath[NROWS * HDIM];       // fp16 cat (GEMM input)
__device__ float  g_catf[NROWS * HDIM];       // fp32 cat (update input)
__device__ float  g_interf[NELEM];

// transposed fp16 weights (B operands, K-major [N,K])
__device__ __half g_WqT[HDIM * FDIM];
__device__ __half g_W01T[HDIM * HDIM];
__device__ __half g_W02T[FDIM * HDIM];
__device__ __half g_W11T[HDIM * HDIM];
__device__ __half g_W12T[FDIM * HDIM];
__device__ __half g_Wi1T[HDIM * HDIM];
__device__ __half g_Wi2T[FDIM * HDIM];

__device__ float g_sp0, g_sp1, g_p0, g_u;
__device__ float g_cA[STEPS], g_rsqa[STEPS], g_qi[STEPS], g_ncoef[STEPS];
__device__ unsigned g_key[STEPS][2];
__device__ unsigned g_key_init[2];

// ---------------------------------------------------------------------------
// PTX helpers (baseline ISA — compute_103 target has no tcgen05)
// ---------------------------------------------------------------------------
__device__ __forceinline__ uint32_t smem_to_u32(const void* p) {
    uint32_t a;
    asm("{ .reg .u64 t; cvta.to.shared.u64 t, %1; cvt.u32.u64 %0, t; }"
        : "=r"(a) : "l"(p));
    return a;
}
__device__ __forceinline__ void cp16(uint32_t dst, const void* src) {
    asm volatile("cp.async.cg.shared.global [%0], [%1], 16;"
                 :: "r"(dst), "l"(src) : "memory");
}
#define CP_COMMIT() asm volatile("cp.async.commit_group;" ::: "memory")
#define LDSM4(R, addr) \
    asm volatile("ldmatrix.sync.aligned.m8n8.x4.shared.b16 {%0,%1,%2,%3}, [%4];" \
                 : "=r"((R)[0]), "=r"((R)[1]), "=r"((R)[2]), "=r"((R)[3]) : "r"(addr))
__device__ __forceinline__ void mma_f16(float* d, const uint32_t* a, const uint32_t* b) {
    asm volatile("mma.sync.aligned.m16n8k16.row.col.f32.f16.f16.f32 "
                 "{%0,%1,%2,%3}, {%4,%5,%6,%7}, {%8,%9}, {%0,%1,%2,%3};"
                 : "+f"(d[0]), "+f"(d[1]), "+f"(d[2]), "+f"(d[3])
                 : "r"(a[0]), "r"(a[1]), "r"(a[2]), "r"(a[3]), "r"(b[0]), "r"(b[1]));
}

// ---------------------------------------------------------------------------
// Threefry-2x32 (JAX partitionable mode)
// ---------------------------------------------------------------------------
__device__ __forceinline__ void tf2x32(unsigned k0, unsigned k1,
                                       unsigned x0, unsigned x1,
                                       unsigned& o0, unsigned& o1) {
    unsigned ks2 = k0 ^ k1 ^ 0x1BD11BDAu;
    x0 += k0; x1 += k1;
#define TF_RND(r) { x0 += x1; x1 = __funnelshift_l(x1, x1, (r)); x1 ^= x0; }
    TF_RND(13) TF_RND(15) TF_RND(26) TF_RND(6)
    x0 += k1;  x1 += ks2 + 1u;
    TF_RND(17) TF_RND(29) TF_RND(16) TF_RND(24)
    x0 += ks2; x1 += k0 + 2u;
    TF_RND(13) TF_RND(15) TF_RND(26) TF_RND(6)
    x0 += k0;  x1 += k1 + 3u;
    TF_RND(17) TF_RND(29) TF_RND(16) TF_RND(24)
    x0 += k1;  x1 += ks2 + 4u;
    TF_RND(13) TF_RND(15) TF_RND(26) TF_RND(6)
    x0 += ks2; x1 += k0 + 5u;
#undef TF_RND
    o0 = x0; o1 = x1;
}
__device__ __forceinline__ unsigned tf_bits(unsigned k0, unsigned k1, unsigned i) {
    unsigned o0, o1;
    tf2x32(k0, k1, 0u, i, o0, o1);
    return o0 ^ o1;
}
__device__ __forceinline__ float bits_to_normal(unsigned b) {
    float u = __uint_as_float((b >> 9) | 0x3f800000u) - 1.0f;
    const float LO = -0.99999994f;
    float v = fmaxf(fmaf(u, 2.0f, LO), LO);
    return 1.41421356f * erfinvf(v);
}

// ---------------------------------------------------------------------------
// Prep: per-step scalars, keys, measurement u
// ---------------------------------------------------------------------------
__global__ void prep_kernel(const float* __restrict__ alpha_amp,
                            const float* __restrict__ beta_amp,
                            const float* __restrict__ phase_cos) {
    int s = threadIdx.x;
    float A = *alpha_amp, B = *beta_amp, pc = *phase_cos;
    float a2 = A * A, b2 = B * B;
    float p0 = a2 / (a2 + b2), p1 = b2 / (a2 + b2);
    if (s == 0) { g_p0 = p0; g_sp0 = sqrtf(p0); g_sp1 = sqrtf(p1); }
    if (s < STEPS) {
        int t = (STEPS - 1) - s;
        const float delta = (0.02f - 1e-4f) / 99.0f;
        float sched_t = 1e-4f + (float)t * delta;
        float alpha = fmaxf(1.0f - sched_t, 1e-8f);
        float alpha_prev = (t > 0) ? (1.0f - (1e-4f + (float)(t - 1) * delta)) : 1.0f;
        float one_m_a = 1.0f - alpha;
        g_cA[s]   = one_m_a / sqrtf(fmaxf(one_m_a, 1e-8f));
        g_rsqa[s] = 1.0f / sqrtf(alpha);
        float decay = expf(-0.1f);
        float coh = 1.0f;
        for (int i = 0; i < s; i++) coh *= decay;
        float qi = 2.0f * sqrtf(p0 * p1) * pc * coh;
        g_qi[s] = qi;
        float sig2 = (1.0f - alpha_prev) / (1.0f - alpha) * (1.0f - alpha / alpha_prev);
        g_ncoef[s] = (t > 0) ? (sqrtf(fmaxf(sig2, 0.0f)) + 0.1f * fabsf(qi)) : 0.0f;
        unsigned o0, o1;
        tf2x32(0u, 1u, 0u, (unsigned)t, o0, o1);
        g_key[s][0] = o0; g_key[s][1] = o1;
    }
    if (s == STEPS) {
        unsigned o0, o1;
        tf2x32(0u, 1u, 0u, 10000u, o0, o1);
        g_key_init[0] = o0; g_key_init[1] = o1;
    }
    if (s == STEPS + 1) {
        unsigned k0, k1;
        tf2x32(0u, 1u, 0u, 99999u, k0, k1);
        unsigned b = tf_bits(k0, k1, 0u);
        g_u = __uint_as_float((b >> 9) | 0x3f800000u) - 1.0f;
    }
}

// ---------------------------------------------------------------------------
// Weight transpose + fp16 convert:  W[K,N] -> WT[N,K]
// ---------------------------------------------------------------------------
__global__ __launch_bounds__(256) void wprep_kernel(const float* __restrict__ W,
                                                    __half* __restrict__ T,
                                                    int K, int N) {
    int i = blockIdx.x * 256 + threadIdx.x;
    if (i >= K * N) return;
    int k = i / N, n = i - k * N;
    T[(size_t)n * K + k] = __float2half(W[i]);
}

// ---------------------------------------------------------------------------
// x0 init: normal + fp16 copy
// ---------------------------------------------------------------------------
__global__ __launch_bounds__(256) void init_kernel() {
    int j = blockIdx.x * 256 + threadIdx.x;
    float v = bits_to_normal(tf_bits(g_key_init[0], g_key_init[1], (unsigned)j));
    g_x[j] = v;
    g_xh[j] = __float2half(v);
}

// ---------------------------------------------------------------------------
// fp16 HMMA GEMM (mma.sync m16n8k16), single product.
// C = act(A @ B^T + bias);  A [M,Ka] fp16, B [N,Ka] fp16, both K-major.
// CTA 128x128, BK=32, 8 warps (2x4), warp tile 64x32; 3-stage cp.async.
// SMEM stage: A(0..10240) B(10240..20480); row pitch 80B (40 halves).
// OUTM: 0 = fp16 out, 1 = fp32 out, 2 = fp16 + fp32 out.
// ---------------------------------------------------------------------------
#define SM_STAGE 20480
#define SMEM_TOTAL (3 * SM_STAGE)

template <int ACT, int OUTM>
__global__ __launch_bounds__(256, 2)
void mm_kernel(const __half* __restrict__ A, int Ka,
               const __half* __restrict__ B,
               const float* __restrict__ bias,
               __half* __restrict__ Ch, float* __restrict__ Cf,
               int ldc, int col_off) {
    extern __shared__ char smem[];
    const uint32_t sb = smem_to_u32(smem);
    const int tid = threadIdx.x, lane = tid & 31, wid = tid >> 5;
    const int wr = wid >> 2, wc = wid & 3;            // warp grid 2x4
    const int m0 = blockIdx.y * 128, n0 = blockIdx.x * 128;
    const int NC = Ka / 32;

    float acc[4][4][4];
#pragma unroll
    for (int i = 0; i < 4; i++)
#pragma unroll
        for (int j = 0; j < 4; j++)
#pragma unroll
            for (int q = 0; q < 4; q++) acc[i][j][q] = 0.0f;

    // stage loader: 2 (row,chunk) slots per thread per matrix
    auto issue = [&](int c) {
        int k0 = c * 32;
        uint32_t so = sb + (c % 3) * SM_STAGE;
#pragma unroll
        for (int i = 0; i < 2; i++) {
            int idx = tid + i * 256;              // 0..511
            int r = idx >> 2, cc = idx & 3;       // row 0..127, 16B chunk 0..3
            uint32_t d = so + r * 80 + cc * 16;
            size_t go = (size_t)r * Ka + k0 + cc * 8;
            cp16(d,         A + (size_t)m0 * Ka + go);
            cp16(d + 10240, B + (size_t)n0 * Ka + go);
        }
        CP_COMMIT();
    };

    issue(0);
    if (NC > 1) issue(1);
    if (NC > 2) issue(2);

    for (int c = 0; c < NC; c++) {
        int rem = NC - 1 - c;                 // groups that may stay in flight
        if (rem >= 2)      asm volatile("cp.async.wait_group 2;" ::: "memory");
        else if (rem == 1) asm volatile("cp.async.wait_group 1;" ::: "memory");
        else               asm volatile("cp.async.wait_group 0;" ::: "memory");
        __syncthreads();

        uint32_t so = sb + (c % 3) * SM_STAGE;
#pragma unroll
        for (int ks = 0; ks < 2; ks++) {
            uint32_t ah[4][4];
            {
                int arow = wr * 64 + (lane & 15);
                uint32_t acol = (uint32_t)(ks * 16 + ((lane >> 4) << 3)) * 2;
#pragma unroll
                for (int mt = 0; mt < 4; mt++)
                    LDSM4(ah[mt], so + (uint32_t)(arow + mt * 16) * 80 + acol);
            }
            uint32_t bh[2][4];
            {
                int g = lane >> 3;
                int brow = wc * 32 + (lane & 7) + ((g >> 1) << 3);
                uint32_t bcol = (uint32_t)(ks * 16 + ((g & 1) << 3)) * 2;
#pragma unroll
                for (int p = 0; p < 2; p++)
                    LDSM4(bh[p], so + 10240 + (uint32_t)(brow + p * 16) * 80 + bcol);
            }
#pragma unroll
            for (int mt = 0; mt < 4; mt++)
#pragma unroll
                for (int nt = 0; nt < 4; nt++)
                    mma_f16(acc[mt][nt], ah[mt], &bh[nt >> 1][(nt & 1) * 2]);
        }
        __syncthreads();                      // stage free before reuse
        if (c + 3 < NC) issue(c + 3);
    }

    // ---- epilogue ----------------------------------------------------------
#pragma unroll
    for (int nt = 0; nt < 4; nt++) {
        int colg = n0 + wc * 32 + nt * 8 + (lane & 3) * 2;
        float b0 = bias[colg], b1 = bias[colg + 1];
#pragma unroll
        for (int mt = 0; mt < 4; mt++) {
            int r0 = m0 + wr * 64 + mt * 16 + (lane >> 2);
            float v[4];
            v[0] = acc[mt][nt][0] + b0;
            v[1] = acc[mt][nt][1] + b1;
            v[2] = acc[mt][nt][2] + b0;
            v[3] = acc[mt][nt][3] + b1;
#pragma unroll
            for (int q = 0; q < 4; q++) {
                if (ACT == 1) v[q] = fmaxf(v[q], 0.0f);
                else if (ACT == 2) v[q] = tanhf(v[q]);
                else if (ACT == 3) v[q] = 0.5f * v[q] * (1.0f + erff(v[q] * 0.70710678f));
            }
            if (OUTM != 0) {
                float2* p0 = (float2*)(Cf + (size_t)r0 * ldc + col_off + colg);
                float2* p1 = (float2*)(Cf + (size_t)(r0 + 8) * ldc + col_off + colg);
                *p0 = make_float2(v[0], v[1]);
                *p1 = make_float2(v[2], v[3]);
            }
            if (OUTM != 1) {
                __half2 h01 = __floats2half2_rn(v[0], v[1]);
                __half2 h23 = __floats2half2_rn(v[2], v[3]);
                *(__half2*)(Ch + (size_t)r0 * ldc + col_off + colg) = h01;
                *(__half2*)(Ch + (size_t)(r0 + 8) * ldc + col_off + colg) = h23;
            }
        }
    }
}

// ---------------------------------------------------------------------------
// Fused diffusion update + Threefry noise (fp32 path; writes x + fp16 copy)
// ---------------------------------------------------------------------------
__global__ __launch_bounds__(256) void update_kernel(int s) {
    int j = blockIdx.x * 256 + threadIdx.x;
    float sp0 = g_sp0, sp1 = g_sp1;
    float qi = g_qi[s], cA = g_cA[s], rsqa = g_rsqa[s], nc = g_ncoef[s];

    int row = j >> 9, col = j & 511;
    int base = (row << 10) + col;
    float d0 = g_catf[base];
    float d1 = g_catf[base + 512];
    float den = sp0 * d0 + sp1 * d1 + qi * g_interf[j];
    float xn = (g_x[j] - cA * den) * rsqa;
    if (nc != 0.0f)
        xn += nc * bits_to_normal(tf_bits(g_key[s][0], g_key[s][1], (unsigned)j));
    g_x[j] = xn;
    g_xh[j] = __float2half(xn);
}

__global__ __launch_bounds__(256) void final_kernel(const float* __restrict__ real,
                                                    float* __restrict__ out) {
    int i = blockIdx.x * 256 + threadIdx.x;
    float x = g_x[i];
    out[i] = (g_u < g_p0) ? (0.7f * x + 0.3f * real[i]) : x;
}

// ---------------------------------------------------------------------------
// Launch
// ---------------------------------------------------------------------------
extern "C" void kernel_launch(void* const* d_in, const int* in_sizes, int n_in,
                              void* d_out, int out_size) {
    const float *real, *Wq, *bq, *W01, *b01, *W02, *b02, *W11, *b11;
    const float *W12, *b12, *Wi1, *bi1, *Wi2, *bi2, *a_amp, *b_amp, *pc;

    if (in_sizes[0] == NELEM) {
        int o = (n_in >= 2 && in_sizes[1] == 1) ? 2 : 1;
        real = (const float*)d_in[0];
        Wq   = (const float*)d_in[o + 0];  bq  = (const float*)d_in[o + 1];
        W01  = (const float*)d_in[o + 2];  b01 = (const float*)d_in[o + 3];
        W02  = (const float*)d_in[o + 4];  b02 = (const float*)d_in[o + 5];
        W11  = (const float*)d_in[o + 6];  b11 = (const float*)d_in[o + 7];
        W12  = (const float*)d_in[o + 8];  b12 = (const float*)d_in[o + 9];
        Wi1  = (const float*)d_in[o + 10]; bi1 = (const float*)d_in[o + 11];
        Wi2  = (const float*)d_in[o + 12]; bi2 = (const float*)d_in[o + 13];
        a_amp = (const float*)d_in[o + 14];
        b_amp = (const float*)d_in[o + 15];
        pc    = (const float*)d_in[o + 16];
    } else {
        W01 = (const float*)d_in[0];  W02 = (const float*)d_in[1];
        W11 = (const float*)d_in[2];  W12 = (const float*)d_in[3];
        Wi1 = (const float*)d_in[4];  Wi2 = (const float*)d_in[5];
        Wq  = (const float*)d_in[6];  a_amp = (const float*)d_in[7];
        b01 = (const float*)d_in[8];  b02 = (const float*)d_in[9];
        b11 = (const float*)d_in[10]; b12 = (const float*)d_in[11];
        b_amp = (const float*)d_in[12];
        bi1 = (const float*)d_in[13]; bi2 = (const float*)d_in[14];
        bq  = (const float*)d_in[15]; pc  = (const float*)d_in[16];
        real = (const float*)d_in[17];
    }
    float* out = (float*)d_out;

    void *p;
    #define SYMH(var, sym) cudaGetSymbolAddress(&p, sym); auto* var = (__half*)p;
    SYMH(xh, g_xh)
    SYMH(qfh, g_qfh)
    SYMH(hh, g_hh)
    SYMH(cath, g_cath)
    SYMH(WqT, g_WqT)
    SYMH(W01T, g_W01T)
    SYMH(W02T, g_W02T)
    SYMH(W11T, g_W11T)
    SYMH(W12T, g_W12T)
    SYMH(Wi1T, g_Wi1T)
    SYMH(Wi2T, g_Wi2T)
    #undef SYMH
    cudaGetSymbolAddress(&p, g_interf); float* itf  = (float*)p;
    cudaGetSymbolAddress(&p, g_catf);   float* catf = (float*)p;

    cudaFuncSetAttribute(mm_kernel<1, 0>, cudaFuncAttributeMaxDynamicSharedMemorySize, SMEM_TOTAL);
    cudaFuncSetAttribute(mm_kernel<2, 0>, cudaFuncAttributeMaxDynamicSharedMemorySize, SMEM_TOTAL);
    cudaFuncSetAttribute(mm_kernel<3, 0>, cudaFuncAttributeMaxDynamicSharedMemorySize, SMEM_TOTAL);
    cudaFuncSetAttribute(mm_kernel<0, 1>, cudaFuncAttributeMaxDynamicSharedMemorySize, SMEM_TOTAL);
    cudaFuncSetAttribute(mm_kernel<0, 2>, cudaFuncAttributeMaxDynamicSharedMemorySize, SMEM_TOTAL);

    prep_kernel<<<1, 64>>>(a_amp, b_amp, pc);
    init_kernel<<<NELEM / 256, 256>>>();

    // one-time weight transpose + fp16 convert
    wprep_kernel<<<(FDIM * HDIM + 255) / 256, 256>>>(Wq,  WqT,  FDIM, HDIM);
    wprep_kernel<<<(HDIM * HDIM + 255) / 256, 256>>>(W01, W01T, HDIM, HDIM);
    wprep_kernel<<<(HDIM * FDIM + 255) / 256, 256>>>(W02, W02T, HDIM, FDIM);
    wprep_kernel<<<(HDIM * HDIM + 255) / 256, 256>>>(W11, W11T, HDIM, HDIM);
    wprep_kernel<<<(HDIM * FDIM + 255) / 256, 256>>>(W12, W12T, HDIM, FDIM);
    wprep_kernel<<<(HDIM * HDIM + 255) / 256, 256>>>(Wi1, Wi1T, HDIM, HDIM);
    wprep_kernel<<<(HDIM * FDIM + 255) / 256, 256>>>(Wi2, Wi2T, HDIM, FDIM);

    dim3 gH(HDIM / 128, NROWS / 128);   // (8, 64)
    dim3 gF(FDIM / 128, NROWS / 128);   // (4, 64)

    for (int s = 0; s < STEPS; s++) {
        // qf = relu(x @ Wq + bq)
        mm_kernel<1, 0><<<gH, 256, SMEM_TOTAL>>>(xh, FDIM, WqT, bq,
                                                 qfh, nullptr, HDIM, 0);
        // h0 = relu(qf @ W01 + b01)
        mm_kernel<1, 0><<<gH, 256, SMEM_TOTAL>>>(qfh, HDIM, W01T, b01,
                                                 hh, nullptr, HDIM, 0);
        // d0 = h0 @ W02 + b02 -> cat[:, 0:512] (fp16 + fp32)
        mm_kernel<0, 2><<<gF, 256, SMEM_TOTAL>>>(hh, HDIM, W02T, b02,
                                                 cath, catf, HDIM, 0);
        // h1 = tanh(qf @ W11 + b11)
        mm_kernel<2, 0><<<gH, 256, SMEM_TOTAL>>>(qfh, HDIM, W11T, b11,
                                                 hh, nullptr, HDIM, 0);
        // d1 = h1 @ W12 + b12 -> cat[:, 512:1024] (fp16 + fp32)
        mm_kernel<0, 2><<<gF, 256, SMEM_TOTAL>>>(hh, HDIM, W12T, b12,
                                                 cath, catf, HDIM, FDIM);
        // hg = gelu(cat @ Wi1 + bi1)
        mm_kernel<3, 0><<<gH, 256, SMEM_TOTAL>>>(cath, HDIM, Wi1T, bi1,
                                                 hh, nullptr, HDIM, 0);
        // interf = hg @ Wi2 + bi2  (fp32 out)
        mm_kernel<0, 1><<<gF, 256, SMEM_TOTAL>>>(hh, HDIM, Wi2T, bi2,
                                                 nullptr, itf, FDIM, 0);
        // diffusion update + noise
        update_kernel<<<NELEM / 256, 256>>>(s);
    }

    final_kernel<<<NELEM / 256, 256>>>(real, out);
}

// round 10
// speedup vs baseline: 7.0190x; 1.1473x over previous
#include <cuda_runtime.h>
#include <cuda_fp16.h>
#include <cstdint>
#include <cstdio>

// ---------------------------------------------------------------------------
// Problem constants
// ---------------------------------------------------------------------------
#define NROWS 8192
#define FDIM  512
#define HDIM  1024
#define STEPS 50
#define NELEM (NROWS * FDIM)          // 4194304

// ---------------------------------------------------------------------------
// Scratch (device globals: allocation-free rule)
// ---------------------------------------------------------------------------
__device__ float  g_x[NELEM];                 // fp32 diffusion state
__device__ __half g_xh[NELEM];                // fp16 of x (GEMM input)
__device__ __half g_qfh[NROWS * HDIM];
__device__ __half g_h01[NROWS * 2 * HDIM];    // fused [h0 | h1], ld = 2048
__device__ __half g_hh[NROWS * HDIM];         // gelu hidden
__device__ __half g_cath[NROWS * HDIM];       // fp16 cat (GEMM input)
__device__ float  g_catf[NROWS * HDIM];       // fp32 cat (update input)
__device__ float  g_interf[NELEM];

// transposed fp16 weights (B operands, K-major [N,K])
__device__ __half g_WqT[HDIM * FDIM];
__device__ __half g_W0111T[2 * HDIM * HDIM];  // stacked [W01T ; W11T]
__device__ __half g_W02T[FDIM * HDIM];
__device__ __half g_W12T[FDIM * HDIM];
__device__ __half g_Wi1T[HDIM * HDIM];
__device__ __half g_Wi2T[FDIM * HDIM];

__device__ float g_sp0, g_sp1, g_p0, g_u;
__device__ float g_cA[STEPS], g_rsqa[STEPS], g_qi[STEPS], g_ncoef[STEPS];
__device__ unsigned g_key[STEPS][2];
__device__ unsigned g_key_init[2];

// ---------------------------------------------------------------------------
// PTX helpers (baseline ISA — compute_103 target has no tcgen05)
// ---------------------------------------------------------------------------
__device__ __forceinline__ uint32_t smem_to_u32(const void* p) {
    uint32_t a;
    asm("{ .reg .u64 t; cvta.to.shared.u64 t, %1; cvt.u32.u64 %0, t; }"
        : "=r"(a) : "l"(p));
    return a;
}
__device__ __forceinline__ void cp16(uint32_t dst, const void* src) {
    asm volatile("cp.async.cg.shared.global [%0], [%1], 16;"
                 :: "r"(dst), "l"(src) : "memory");
}
#define CP_COMMIT() asm volatile("cp.async.commit_group;" ::: "memory")
#define LDSM4(R, addr) \
    asm volatile("ldmatrix.sync.aligned.m8n8.x4.shared.b16 {%0,%1,%2,%3}, [%4];" \
                 : "=r"((R)[0]), "=r"((R)[1]), "=r"((R)[2]), "=r"((R)[3]) : "r"(addr))
__device__ __forceinline__ void mma_f16(float* d, const uint32_t* a, const uint32_t* b) {
    asm volatile("mma.sync.aligned.m16n8k16.row.col.f32.f16.f16.f32 "
                 "{%0,%1,%2,%3}, {%4,%5,%6,%7}, {%8,%9}, {%0,%1,%2,%3};"
                 : "+f"(d[0]), "+f"(d[1]), "+f"(d[2]), "+f"(d[3])
                 : "r"(a[0]), "r"(a[1]), "r"(a[2]), "r"(a[3]), "r"(b[0]), "r"(b[1]));
}

// ---------------------------------------------------------------------------
// Threefry-2x32 (JAX partitionable mode)
// ---------------------------------------------------------------------------
__device__ __forceinline__ void tf2x32(unsigned k0, unsigned k1,
                                       unsigned x0, unsigned x1,
                                       unsigned& o0, unsigned& o1) {
    unsigned ks2 = k0 ^ k1 ^ 0x1BD11BDAu;
    x0 += k0; x1 += k1;
#define TF_RND(r) { x0 += x1; x1 = __funnelshift_l(x1, x1, (r)); x1 ^= x0; }
    TF_RND(13) TF_RND(15) TF_RND(26) TF_RND(6)
    x0 += k1;  x1 += ks2 + 1u;
    TF_RND(17) TF_RND(29) TF_RND(16) TF_RND(24)
    x0 += ks2; x1 += k0 + 2u;
    TF_RND(13) TF_RND(15) TF_RND(26) TF_RND(6)
    x0 += k0;  x1 += k1 + 3u;
    TF_RND(17) TF_RND(29) TF_RND(16) TF_RND(24)
    x0 += k1;  x1 += ks2 + 4u;
    TF_RND(13) TF_RND(15) TF_RND(26) TF_RND(6)
    x0 += ks2; x1 += k0 + 5u;
#undef TF_RND
    o0 = x0; o1 = x1;
}
__device__ __forceinline__ unsigned tf_bits(unsigned k0, unsigned k1, unsigned i) {
    unsigned o0, o1;
    tf2x32(k0, k1, 0u, i, o0, o1);
    return o0 ^ o1;
}
__device__ __forceinline__ float bits_to_normal(unsigned b) {
    float u = __uint_as_float((b >> 9) | 0x3f800000u) - 1.0f;
    const float LO = -0.99999994f;
    float v = fmaxf(fmaf(u, 2.0f, LO), LO);
    return 1.41421356f * erfinvf(v);
}

// ---------------------------------------------------------------------------
// Prep: per-step scalars, keys, measurement u
// ---------------------------------------------------------------------------
__global__ void prep_kernel(const float* __restrict__ alpha_amp,
                            const float* __restrict__ beta_amp,
                            const float* __restrict__ phase_cos) {
    int s = threadIdx.x;
    float A = *alpha_amp, B = *beta_amp, pc = *phase_cos;
    float a2 = A * A, b2 = B * B;
    float p0 = a2 / (a2 + b2), p1 = b2 / (a2 + b2);
    if (s == 0) { g_p0 = p0; g_sp0 = sqrtf(p0); g_sp1 = sqrtf(p1); }
    if (s < STEPS) {
        int t = (STEPS - 1) - s;
        const float delta = (0.02f - 1e-4f) / 99.0f;
        float sched_t = 1e-4f + (float)t * delta;
        float alpha = fmaxf(1.0f - sched_t, 1e-8f);
        float alpha_prev = (t > 0) ? (1.0f - (1e-4f + (float)(t - 1) * delta)) : 1.0f;
        float one_m_a = 1.0f - alpha;
        g_cA[s]   = one_m_a / sqrtf(fmaxf(one_m_a, 1e-8f));
        g_rsqa[s] = 1.0f / sqrtf(alpha);
        float decay = expf(-0.1f);
        float coh = 1.0f;
        for (int i = 0; i < s; i++) coh *= decay;
        float qi = 2.0f * sqrtf(p0 * p1) * pc * coh;
        g_qi[s] = qi;
        float sig2 = (1.0f - alpha_prev) / (1.0f - alpha) * (1.0f - alpha / alpha_prev);
        g_ncoef[s] = (t > 0) ? (sqrtf(fmaxf(sig2, 0.0f)) + 0.1f * fabsf(qi)) : 0.0f;
        unsigned o0, o1;
        tf2x32(0u, 1u, 0u, (unsigned)t, o0, o1);
        g_key[s][0] = o0; g_key[s][1] = o1;
    }
    if (s == STEPS) {
        unsigned o0, o1;
        tf2x32(0u, 1u, 0u, 10000u, o0, o1);
        g_key_init[0] = o0; g_key_init[1] = o1;
    }
    if (s == STEPS + 1) {
        unsigned k0, k1;
        tf2x32(0u, 1u, 0u, 99999u, k0, k1);
        unsigned b = tf_bits(k0, k1, 0u);
        g_u = __uint_as_float((b >> 9) | 0x3f800000u) - 1.0f;
    }
}

// ---------------------------------------------------------------------------
// Single merged weight transpose + fp16 convert (7 segments via blockIdx.y)
// ---------------------------------------------------------------------------
__global__ __launch_bounds__(256)
void wprep_all_kernel(const float* __restrict__ Wq,  const float* __restrict__ W01,
                      const float* __restrict__ W11, const float* __restrict__ W02,
                      const float* __restrict__ W12, const float* __restrict__ Wi1,
                      const float* __restrict__ Wi2) {
    int i = blockIdx.x * 256 + threadIdx.x;
    int seg = blockIdx.y;
    const float* src;
    __half* dst;
    int K, N;
    size_t dstoff = 0;
    switch (seg) {
        case 0: src = Wq;  dst = g_WqT;    K = FDIM; N = HDIM; break;
        case 1: src = W01; dst = g_W0111T; K = HDIM; N = HDIM; break;
        case 2: src = W11; dst = g_W0111T; K = HDIM; N = HDIM; dstoff = (size_t)HDIM * HDIM; break;
        case 3: src = W02; dst = g_W02T;   K = HDIM; N = FDIM; break;
        case 4: src = W12; dst = g_W12T;   K = HDIM; N = FDIM; break;
        case 5: src = Wi1; dst = g_Wi1T;   K = HDIM; N = HDIM; break;
        default: src = Wi2; dst = g_Wi2T;  K = HDIM; N = FDIM; break;
    }
    if (i >= K * N) return;
    int k = i / N, n = i - k * N;
    dst[dstoff + (size_t)n * K + k] = __float2half(src[i]);
}

// ---------------------------------------------------------------------------
// x0 init: normal + fp16 copy
// ---------------------------------------------------------------------------
__global__ __launch_bounds__(256) void init_kernel() {
    int j = blockIdx.x * 256 + threadIdx.x;
    float v = bits_to_normal(tf_bits(g_key_init[0], g_key_init[1], (unsigned)j));
    g_x[j] = v;
    g_xh[j] = __float2half(v);
}

// ---------------------------------------------------------------------------
// fp16 HMMA GEMM (mma.sync m16n8k16).
// C = act(A @ B^T + bias);  A [M,*] lda-strided, B [N,Ka] K-major.
// CTA 128x128, BK=64, 8 warps (2x4), warp tile 64x32; 2-stage cp.async.
// SMEM stage: A(0..18432) B(18432..36864); pitch 144B (64 halves + 16B pad).
// ACT: 0=none 1=relu 2=tanh 3=gelu 4=relu if n0<HDIM else tanh (uses bias2).
// OUTM: 0 = fp16 out, 1 = fp32 out, 2 = fp16 + fp32 out.
// ---------------------------------------------------------------------------
#define SM_PITCH 144
#define SM_HALF  (128 * SM_PITCH)           // 18432
#define SM_STAGE (2 * SM_HALF)              // 36864
#define SMEM_TOTAL (2 * SM_STAGE)           // 73728

template <int ACT, int OUTM>
__global__ __launch_bounds__(256, 2)
void mm_kernel(const __half* __restrict__ A, int lda, int Ka,
               const __half* __restrict__ B,
               const float* __restrict__ bias, const float* __restrict__ bias2,
               __half* __restrict__ Ch, float* __restrict__ Cf,
               int ldc, int col_off) {
    extern __shared__ char smem[];
    const uint32_t sb = smem_to_u32(smem);
    const int tid = threadIdx.x, lane = tid & 31, wid = tid >> 5;
    const int wr = wid >> 2, wc = wid & 3;
    const int m0 = blockIdx.y * 128, n0 = blockIdx.x * 128;
    const int NC = Ka / 64;

    float acc[4][4][4];
#pragma unroll
    for (int i = 0; i < 4; i++)
#pragma unroll
        for (int j = 0; j < 4; j++)
#pragma unroll
            for (int q = 0; q < 4; q++) acc[i][j][q] = 0.0f;

    auto issue = [&](int c) {
        int k0 = c * 64;
        uint32_t so = sb + (c & 1) * SM_STAGE;
#pragma unroll
        for (int i = 0; i < 4; i++) {
            int idx = tid + i * 256;              // 0..1023
            int r = idx >> 3, cc = idx & 7;       // row, 16B chunk
            uint32_t d = so + r * SM_PITCH + cc * 16;
            cp16(d,           A + (size_t)(m0 + r) * lda + k0 + cc * 8);
            cp16(d + SM_HALF, B + (size_t)(n0 + r) * Ka  + k0 + cc * 8);
        }
        CP_COMMIT();
    };

    issue(0);
    if (NC > 1) issue(1);

    for (int c = 0; c < NC; c++) {
        if (c + 1 < NC) asm volatile("cp.async.wait_group 1;" ::: "memory");
        else            asm volatile("cp.async.wait_group 0;" ::: "memory");
        __syncthreads();

        uint32_t so = sb + (c & 1) * SM_STAGE;
#pragma unroll
        for (int ks = 0; ks < 4; ks++) {
            uint32_t ah[4][4];
            {
                int arow = wr * 64 + (lane & 15);
                uint32_t acol = (uint32_t)(ks * 16 + ((lane >> 4) << 3)) * 2;
#pragma unroll
                for (int mt = 0; mt < 4; mt++)
                    LDSM4(ah[mt], so + (uint32_t)(arow + mt * 16) * SM_PITCH + acol);
            }
            uint32_t bh[2][4];
            {
                int g = lane >> 3;
                int brow = wc * 32 + (lane & 7) + ((g >> 1) << 3);
                uint32_t bcol = (uint32_t)(ks * 16 + ((g & 1) << 3)) * 2;
#pragma unroll
                for (int p = 0; p < 2; p++)
                    LDSM4(bh[p], so + SM_HALF + (uint32_t)(brow + p * 16) * SM_PITCH + bcol);
            }
#pragma unroll
            for (int mt = 0; mt < 4; mt++)
#pragma unroll
                for (int nt = 0; nt < 4; nt++)
                    mma_f16(acc[mt][nt], ah[mt], &bh[nt >> 1][(nt & 1) * 2]);
        }
        __syncthreads();
        if (c + 2 < NC) issue(c + 2);
    }

    // ---- epilogue ----------------------------------------------------------
    const bool tanh_side = (ACT == 4) && (n0 >= HDIM);
    const float* bp = (ACT == 4 && tanh_side) ? bias2 : bias;
    const int colbase = (ACT == 4 && tanh_side) ? (n0 - HDIM) : n0;
#pragma unroll
    for (int nt = 0; nt < 4; nt++) {
        int coll = wc * 32 + nt * 8 + (lane & 3) * 2;     // 0..127 in tile
        int colg = n0 + coll;                              // global column
        float b0 = bp[colbase + coll], b1 = bp[colbase + coll + 1];
#pragma unroll
        for (int mt = 0; mt < 4; mt++) {
            int r0 = m0 + wr * 64 + mt * 16 + (lane >> 2);
            float v[4];
            v[0] = acc[mt][nt][0] + b0;
            v[1] = acc[mt][nt][1] + b1;
            v[2] = acc[mt][nt][2] + b0;
            v[3] = acc[mt][nt][3] + b1;
#pragma unroll
            for (int q = 0; q < 4; q++) {
                if (ACT == 1) v[q] = fmaxf(v[q], 0.0f);
                else if (ACT == 2) v[q] = tanhf(v[q]);
                else if (ACT == 3) v[q] = 0.5f * v[q] * (1.0f + erff(v[q] * 0.70710678f));
                else if (ACT == 4) v[q] = tanh_side ? tanhf(v[q]) : fmaxf(v[q], 0.0f);
            }
            if (OUTM != 0) {
                *(float2*)(Cf + (size_t)r0 * ldc + col_off + colg) = make_float2(v[0], v[1]);
                *(float2*)(Cf + (size_t)(r0 + 8) * ldc + col_off + colg) = make_float2(v[2], v[3]);
            }
            if (OUTM != 1) {
                *(__half2*)(Ch + (size_t)r0 * ldc + col_off + colg) = __floats2half2_rn(v[0], v[1]);
                *(__half2*)(Ch + (size_t)(r0 + 8) * ldc + col_off + colg) = __floats2half2_rn(v[2], v[3]);
            }
        }
    }
}

// ---------------------------------------------------------------------------
// Fused diffusion update + Threefry noise (fp32 path; writes x + fp16 copy)
// ---------------------------------------------------------------------------
__global__ __launch_bounds__(256) void update_kernel(int s) {
    int j = blockIdx.x * 256 + threadIdx.x;
    float sp0 = g_sp0, sp1 = g_sp1;
    float qi = g_qi[s], cA = g_cA[s], rsqa = g_rsqa[s], nc = g_ncoef[s];

    int row = j >> 9, col = j & 511;
    int base = (row << 10) + col;
    float d0 = g_catf[base];
    float d1 = g_catf[base + 512];
    float den = sp0 * d0 + sp1 * d1 + qi * g_interf[j];
    float xn = (g_x[j] - cA * den) * rsqa;
    if (nc != 0.0f)
        xn += nc * bits_to_normal(tf_bits(g_key[s][0], g_key[s][1], (unsigned)j));
    g_x[j] = xn;
    g_xh[j] = __float2half(xn);
}

__global__ __launch_bounds__(256) void final_kernel(const float* __restrict__ real,
                                                    float* __restrict__ out) {
    int i = blockIdx.x * 256 + threadIdx.x;
    float x = g_x[i];
    out[i] = (g_u < g_p0) ? (0.7f * x + 0.3f * real[i]) : x;
}

// ---------------------------------------------------------------------------
// Launch
// ---------------------------------------------------------------------------
extern "C" void kernel_launch(void* const* d_in, const int* in_sizes, int n_in,
                              void* d_out, int out_size) {
    const float *real, *Wq, *bq, *W01, *b01, *W02, *b02, *W11, *b11;
    const float *W12, *b12, *Wi1, *bi1, *Wi2, *bi2, *a_amp, *b_amp, *pc;

    if (in_sizes[0] == NELEM) {
        int o = (n_in >= 2 && in_sizes[1] == 1) ? 2 : 1;
        real = (const float*)d_in[0];
        Wq   = (const float*)d_in[o + 0];  bq  = (const float*)d_in[o + 1];
        W01  = (const float*)d_in[o + 2];  b01 = (const float*)d_in[o + 3];
        W02  = (const float*)d_in[o + 4];  b02 = (const float*)d_in[o + 5];
        W11  = (const float*)d_in[o + 6];  b11 = (const float*)d_in[o + 7];
        W12  = (const float*)d_in[o + 8];  b12 = (const float*)d_in[o + 9];
        Wi1  = (const float*)d_in[o + 10]; bi1 = (const float*)d_in[o + 11];
        Wi2  = (const float*)d_in[o + 12]; bi2 = (const float*)d_in[o + 13];
        a_amp = (const float*)d_in[o + 14];
        b_amp = (const float*)d_in[o + 15];
        pc    = (const float*)d_in[o + 16];
    } else {
        W01 = (const float*)d_in[0];  W02 = (const float*)d_in[1];
        W11 = (const float*)d_in[2];  W12 = (const float*)d_in[3];
        Wi1 = (const float*)d_in[4];  Wi2 = (const float*)d_in[5];
        Wq  = (const float*)d_in[6];  a_amp = (const float*)d_in[7];
        b01 = (const float*)d_in[8];  b02 = (const float*)d_in[9];
        b11 = (const float*)d_in[10]; b12 = (const float*)d_in[11];
        b_amp = (const float*)d_in[12];
        bi1 = (const float*)d_in[13]; bi2 = (const float*)d_in[14];
        bq  = (const float*)d_in[15]; pc  = (const float*)d_in[16];
        real = (const float*)d_in[17];
    }
    float* out = (float*)d_out;

    void *p;
    #define SYMH(var, sym) cudaGetSymbolAddress(&p, sym); auto* var = (__half*)p;
    SYMH(xh, g_xh)
    SYMH(qfh, g_qfh)
    SYMH(h01, g_h01)
    SYMH(hh, g_hh)
    SYMH(cath, g_cath)
    SYMH(WqT, g_WqT)
    SYMH(W0111T, g_W0111T)
    SYMH(W02T, g_W02T)
    SYMH(W12T, g_W12T)
    SYMH(Wi1T, g_Wi1T)
    SYMH(Wi2T, g_Wi2T)
    #undef SYMH
    cudaGetSymbolAddress(&p, g_interf); float* itf  = (float*)p;
    cudaGetSymbolAddress(&p, g_catf);   float* catf = (float*)p;

    cudaFuncSetAttribute(mm_kernel<1, 0>, cudaFuncAttributeMaxDynamicSharedMemorySize, SMEM_TOTAL);
    cudaFuncSetAttribute(mm_kernel<4, 0>, cudaFuncAttributeMaxDynamicSharedMemorySize, SMEM_TOTAL);
    cudaFuncSetAttribute(mm_kernel<3, 0>, cudaFuncAttributeMaxDynamicSharedMemorySize, SMEM_TOTAL);
    cudaFuncSetAttribute(mm_kernel<0, 1>, cudaFuncAttributeMaxDynamicSharedMemorySize, SMEM_TOTAL);
    cudaFuncSetAttribute(mm_kernel<0, 2>, cudaFuncAttributeMaxDynamicSharedMemorySize, SMEM_TOTAL);

    prep_kernel<<<1, 64>>>(a_amp, b_amp, pc);
    init_kernel<<<NELEM / 256, 256>>>();
    wprep_all_kernel<<<dim3(4096, 7), 256>>>(Wq, W01, W11, W02, W12, Wi1, Wi2);

    dim3 gH(HDIM / 128, NROWS / 128);        // (8, 64)
    dim3 gH2(2 * HDIM / 128, NROWS / 128);   // (16, 64) fused h01
    dim3 gF(FDIM / 128, NROWS / 128);        // (4, 64)

    for (int s = 0; s < STEPS; s++) {
        // qf = relu(x @ Wq + bq)
        mm_kernel<1, 0><<<gH, 256, SMEM_TOTAL>>>(xh, FDIM, FDIM, WqT, bq, bq,
                                                 qfh, nullptr, HDIM, 0);
        // [h0|h1] = {relu|tanh}(qf @ [W01;W11]^T + {b01|b11})
        mm_kernel<4, 0><<<gH2, 256, SMEM_TOTAL>>>(qfh, HDIM, HDIM, W0111T, b01, b11,
                                                  h01, nullptr, 2 * HDIM, 0);
        // d0 = h0 @ W02 + b02 -> cat[:, 0:512] (fp16 + fp32)
        mm_kernel<0, 2><<<gF, 256, SMEM_TOTAL>>>(h01, 2 * HDIM, HDIM, W02T, b02, b02,
                                                 cath, catf, HDIM, 0);
        // d1 = h1 @ W12 + b12 -> cat[:, 512:1024] (fp16 + fp32)
        mm_kernel<0, 2><<<gF, 256, SMEM_TOTAL>>>(h01 + HDIM, 2 * HDIM, HDIM, W12T, b12, b12,
                                                 cath, catf, HDIM, FDIM);
        // hg = gelu(cat @ Wi1 + bi1)
        mm_kernel<3, 0><<<gH, 256, SMEM_TOTAL>>>(cath, HDIM, HDIM, Wi1T, bi1, bi1,
                                                 hh, nullptr, HDIM, 0);
        // interf = hg @ Wi2 + bi2  (fp32 out)
        mm_kernel<0, 1><<<gF, 256, SMEM_TOTAL>>>(hh, HDIM, HDIM, Wi2T, bi2, bi2,
                                                 nullptr, itf, FDIM, 0);
        // diffusion update + noise
        update_kernel<<<NELEM / 256, 256>>>(s);
    }

    final_kernel<<<NELEM / 256, 256>>>(real, out);
}